// round 11
// baseline (speedup 1.0000x reference)
#include <cuda_runtime.h>
#include <cuda_bf16.h>
#include <cstdint>

#define BB 4
#define SS 2048
#define FF 1024
#define HH 16
#define DD 64

// ---------------------------------------------------------------------------
// Scratch (allocation-free requirement -> __device__ globals)
// ---------------------------------------------------------------------------
__device__ uint16_t g_wq_h[1048576], g_wq_l[1048576];
__device__ uint16_t g_wk_h[1048576], g_wk_l[1048576];
__device__ uint16_t g_wv_h[1048576], g_wv_l[1048576];
__device__ uint16_t g_fcw_h[1048576], g_fcw_l[1048576];
__device__ uint16_t g_qh_h[16777216], g_qh_l[16777216];   // [B,H,S,D]
__device__ uint16_t g_kh_h[16777216], g_kh_l[16777216];   // [B,H,S,D]
__device__ uint16_t g_vt_h[16777216], g_vt_l[16777216];   // [B,H,D,S]
__device__ uint16_t g_ctx_h[16777216], g_ctx_l[16777216]; // [B,S,F]

// ---------------------------------------------------------------------------
__device__ __forceinline__ uint32_t smem_u32(const void* p) {
    uint32_t a;
    asm("{ .reg .u64 t; cvta.to.shared.u64 t, %1; cvt.u32.u64 %0, t; }"
        : "=r"(a) : "l"(p));
    return a;
}

__device__ __forceinline__ void ldsm4(uint32_t* r, uint32_t addr) {
    asm volatile("ldmatrix.sync.aligned.m8n8.x4.shared.b16 {%0,%1,%2,%3}, [%4];"
                 : "=r"(r[0]), "=r"(r[1]), "=r"(r[2]), "=r"(r[3]) : "r"(addr));
}

__device__ __forceinline__ void mma16816(float* c, const uint32_t* a,
                                         uint32_t b0, uint32_t b1) {
    asm volatile(
        "mma.sync.aligned.m16n8k16.row.col.f32.bf16.bf16.f32 "
        "{%0,%1,%2,%3}, {%4,%5,%6,%7}, {%8,%9}, {%0,%1,%2,%3};"
        : "+f"(c[0]), "+f"(c[1]), "+f"(c[2]), "+f"(c[3])
        : "r"(a[0]), "r"(a[1]), "r"(a[2]), "r"(a[3]), "r"(b0), "r"(b1));
}

__device__ __forceinline__ uint32_t packbf(float a, float b) {
    __nv_bfloat162 t = __floats2bfloat162_rn(a, b);
    return *reinterpret_cast<uint32_t*>(&t);
}

__device__ __forceinline__ void split_pack(float4 v, uint2& hi, uint2& lo) {
    __nv_bfloat16 hx = __float2bfloat16(v.x);
    __nv_bfloat16 hy = __float2bfloat16(v.y);
    __nv_bfloat16 hz = __float2bfloat16(v.z);
    __nv_bfloat16 hw = __float2bfloat16(v.w);
    hi.x = packbf(v.x, v.y);
    hi.y = packbf(v.z, v.w);
    lo.x = packbf(v.x - __bfloat162float(hx), v.y - __bfloat162float(hy));
    lo.y = packbf(v.z - __bfloat162float(hz), v.w - __bfloat162float(hw));
}

__device__ __forceinline__ void store_split(uint16_t* Dh, uint16_t* Dl,
                                            size_t idx, float val) {
    __nv_bfloat16 h = __float2bfloat16(val);
    *(__nv_bfloat16*)&Dh[idx] = h;
    *(__nv_bfloat16*)&Dl[idx] = __float2bfloat16(val - __bfloat162float(h));
}

// ---------------------------------------------------------------------------
__global__ __launch_bounds__(256) void presplit_kernel(
    const float4* __restrict__ W, uint16_t* __restrict__ Wh,
    uint16_t* __restrict__ Wl)
{
#pragma unroll
    for (int u = 0; u < 4; ++u) {
        int i = (blockIdx.x * 4 + u) * 256 + threadIdx.x;
        float4 v = W[i];
        uint2 hi, lo;
        split_pack(v, hi, lo);
        ((uint2*)Wh)[i] = hi;
        ((uint2*)Wl)[i] = lo;
    }
}

// ---------------------------------------------------------------------------
// 3xBF16 mma.sync NT-GEMM, 128 threads (4 warps, 2x2), 64x64 warp tiles.
//  0: proj Q/K : A f32 (split in-kernel) x presplit W -> bf16 [B,H,S,D]
//  1: proj V   : same -> transposed bf16 [B,H,D,S]
//  2: scores   : per bh: bf16 qh @ kh^T * 0.125 -> f32 logits (KC=1)
//  3: ctx      : per bh: attn f32 (split in-kernel) @ vt^T -> ctx bf16
//  4: fc       : bf16 ctx @ fcw^T + b, ReLU -> f32 out
// ---------------------------------------------------------------------------
template <int STAGE>
__global__ __launch_bounds__(128, 2) void mma_gemm(
    const uint16_t* __restrict__ Ah, const uint16_t* __restrict__ Al,
    const float*    __restrict__ Af,
    const uint16_t* __restrict__ Bh, const uint16_t* __restrict__ Bl,
    const float* __restrict__ bias,
    float* __restrict__ Df, uint16_t* __restrict__ Dh, uint16_t* __restrict__ Dl)
{
    constexpr int NT   = (STAGE == 3) ? 64 : 128;
    constexpr int BK   = (STAGE == 2) ? 64 : 32;
    constexpr int KTOT = (STAGE == 2) ? 64 : ((STAGE == 3) ? 2048 : 1024);
    constexpr int KC   = KTOT / BK;
    constexpr int LDA  = (STAGE == 2) ? 64 : ((STAGE == 3) ? 2048 : 1024);
    constexpr int LDB  = (STAGE == 2) ? 64 : ((STAGE == 3) ? 2048 : 1024);
    constexpr int PADX = (STAGE == 2) ? 72 : 40;
    constexpr int KSL  = BK / 16;
    constexpr int WN     = NT / 2;       // warp cols: 64 or 32
    constexpr int NPAIRS = WN / 16;      // 4 or 2
    constexpr int NTILES = 2 * NPAIRS;   // 8 or 4
    constexpr bool A_F32 = (STAGE <= 1) || (STAGE == 3);

    extern __shared__ __align__(16) uint16_t dsm[];
    uint16_t* sA_h = dsm;
    uint16_t* sA_l = sA_h + 128 * PADX;
    uint16_t* sB_h = sA_l + 128 * PADX;
    uint16_t* sB_l = sB_h + NT * PADX;

    const int tid  = threadIdx.x;
    const int wid  = tid >> 5;
    const int lane = tid & 31;
    const int warp_m = wid >> 1;   // 0..1  (64 rows each)
    const int warp_n = wid & 1;    // 0..1  (WN cols each)

    const int m0 = blockIdx.y * 128;
    const int n0 = blockIdx.x * NT;
    const int bh = blockIdx.z;

    if constexpr (STAGE == 2) {
        size_t ao = (size_t)bh * SS * DD + (size_t)m0 * LDA;
        size_t bo = (size_t)bh * SS * DD + (size_t)n0 * LDB;
        Ah += ao; Al += ao; Bh += bo; Bl += bo;
    } else if constexpr (STAGE == 3) {
        Af += (size_t)bh * SS * SS + (size_t)m0 * LDA;
        size_t bo = (size_t)bh * DD * SS;
        Bh += bo; Bl += bo;
    } else if constexpr (A_F32) {
        Af += (size_t)m0 * LDA;
        size_t bo = (size_t)n0 * LDB;
        Bh += bo; Bl += bo;
    } else {
        size_t ao = (size_t)m0 * LDA;
        size_t bo = (size_t)n0 * LDB;
        Ah += ao; Al += ao; Bh += bo; Bl += bo;
    }

    float acc[4][NTILES][4];
#pragma unroll
    for (int mt = 0; mt < 4; ++mt)
#pragma unroll
        for (int nt = 0; nt < NTILES; ++nt)
#pragma unroll
            for (int i = 0; i < 4; ++i) acc[mt][nt][i] = 0.f;

    for (int ch = 0; ch < KC; ++ch) {
        const int k0 = ch * BK;
        if (ch) __syncthreads();

        // ---- stage A tile ----
        if constexpr (A_F32) {
            // 128 rows x 32 f32; 128 threads -> 8 float4 each
#pragma unroll
            for (int i = 0; i < 8; ++i) {
                int f = tid + i * 128;
                int r = f >> 3, c = (f & 7) << 2;
                float4 v = *(const float4*)(Af + (size_t)r * LDA + k0 + c);
                uint2 hi, lo;
                split_pack(v, hi, lo);
                *(uint2*)&sA_h[r * PADX + c] = hi;
                *(uint2*)&sA_l[r * PADX + c] = lo;
            }
        } else {
            constexpr int U4 = BK / 8;
            constexpr int IT = 128 * U4 / 128;
#pragma unroll
            for (int i = 0; i < IT; ++i) {
                int f = tid + i * 128;
                int r = f / U4, c = (f % U4) * 8;
                *(uint4*)&sA_h[r * PADX + c] = *(const uint4*)(Ah + (size_t)r * LDA + k0 + c);
                *(uint4*)&sA_l[r * PADX + c] = *(const uint4*)(Al + (size_t)r * LDA + k0 + c);
            }
        }
        // ---- stage B tile (bf16 presplit) ----
        {
            constexpr int U4 = BK / 8;
            constexpr int IT = NT * U4 / 128;
#pragma unroll
            for (int i = 0; i < IT; ++i) {
                int f = tid + i * 128;
                int r = f / U4, c = (f % U4) * 8;
                *(uint4*)&sB_h[r * PADX + c] = *(const uint4*)(Bh + (size_t)r * LDB + k0 + c);
                *(uint4*)&sB_l[r * PADX + c] = *(const uint4*)(Bl + (size_t)r * LDB + k0 + c);
            }
        }
        __syncthreads();

#pragma unroll
        for (int ks = 0; ks < KSL; ++ks) {
            const int kcol = ks * 16 + (lane >> 4) * 8;
            uint32_t ah[4][4], al[4][4];
#pragma unroll
            for (int mt = 0; mt < 4; ++mt) {
                int row = warp_m * 64 + mt * 16 + (lane & 15);
                ldsm4(ah[mt], smem_u32(&sA_h[row * PADX + kcol]));
                ldsm4(al[mt], smem_u32(&sA_l[row * PADX + kcol]));
            }
            uint32_t bhf[NPAIRS][4], blf[NPAIRS][4];
#pragma unroll
            for (int np = 0; np < NPAIRS; ++np) {
                int nrow = warp_n * WN + np * 16 + (lane & 15);
                ldsm4(bhf[np], smem_u32(&sB_h[nrow * PADX + kcol]));
                ldsm4(blf[np], smem_u32(&sB_l[nrow * PADX + kcol]));
            }
#pragma unroll
            for (int mt = 0; mt < 4; ++mt)
#pragma unroll
                for (int np = 0; np < NPAIRS; ++np)
#pragma unroll
                    for (int sub = 0; sub < 2; ++sub)
                        mma16816(acc[mt][np * 2 + sub], ah[mt],
                                 bhf[np][sub], bhf[np][sub + 2]);
#pragma unroll
            for (int mt = 0; mt < 4; ++mt)
#pragma unroll
                for (int np = 0; np < NPAIRS; ++np)
#pragma unroll
                    for (int sub = 0; sub < 2; ++sub)
                        mma16816(acc[mt][np * 2 + sub], ah[mt],
                                 blf[np][sub], blf[np][sub + 2]);
#pragma unroll
            for (int mt = 0; mt < 4; ++mt)
#pragma unroll
                for (int np = 0; np < NPAIRS; ++np)
#pragma unroll
                    for (int sub = 0; sub < 2; ++sub)
                        mma16816(acc[mt][np * 2 + sub], al[mt],
                                 bhf[np][sub], bhf[np][sub + 2]);
        }
    }

    // ---- epilogue ----
    const int g = lane >> 2;
    const int j = (lane & 3) << 1;
    const int m_base = m0 + warp_m * 64;
    const int n_base = n0 + warp_n * WN;

#pragma unroll
    for (int mt = 0; mt < 4; ++mt) {
#pragma unroll
        for (int nt = 0; nt < NTILES; ++nt) {
#pragma unroll
            for (int e = 0; e < 4; ++e) {
                int row = m_base + mt * 16 + g + (e >> 1) * 8;
                int col = n_base + nt * 8 + j + (e & 1);
                float val = acc[mt][nt][e];
                if constexpr (STAGE == 0) {
                    val += bias[col];
                    int b = row >> 11, s = row & 2047, h = col >> 6, d = col & 63;
                    store_split(Dh, Dl, (((size_t)b * HH + h) * SS + s) * DD + d, val);
                } else if constexpr (STAGE == 1) {
                    val += bias[col];
                    int b = row >> 11, s = row & 2047, h = col >> 6, d = col & 63;
                    store_split(Dh, Dl, (((size_t)b * HH + h) * DD + d) * SS + s, val);
                } else if constexpr (STAGE == 2) {
                    Df[((size_t)bh * SS + row) * SS + col] = val * 0.125f;
                } else if constexpr (STAGE == 3) {
                    int b = bh >> 4, h = bh & 15;
                    store_split(Dh, Dl, ((size_t)b * SS + row) * FF + h * DD + col, val);
                } else {
                    val += bias[col];
                    Df[(size_t)row * FF + col] = fmaxf(val, 0.f);
                }
            }
        }
    }
}

// ---------------------------------------------------------------------------
// Warp-per-row softmax (rows of 2048). Block = 8 warps = 8 rows; no barriers.
// Each lane holds 16 float4 = 64 values in registers; single read, single write.
// ---------------------------------------------------------------------------
__global__ __launch_bounds__(256) void softmax_kernel(float* __restrict__ attn)
{
    const int warp = threadIdx.x >> 5;
    const int lane = threadIdx.x & 31;
    const size_t row = (size_t)blockIdx.x * 8 + warp;
    float4* p4 = (float4*)(attn + row * SS);

    float4 v[16];
    float mx = -1e30f;
#pragma unroll
    for (int i = 0; i < 16; ++i) {
        v[i] = p4[lane + i * 32];
        mx = fmaxf(mx, fmaxf(fmaxf(v[i].x, v[i].y), fmaxf(v[i].z, v[i].w)));
    }
#pragma unroll
    for (int o = 16; o > 0; o >>= 1)
        mx = fmaxf(mx, __shfl_xor_sync(0xffffffffu, mx, o));

    float sum = 0.f;
#pragma unroll
    for (int i = 0; i < 16; ++i) {
        v[i].x = __expf(v[i].x - mx);
        v[i].y = __expf(v[i].y - mx);
        v[i].z = __expf(v[i].z - mx);
        v[i].w = __expf(v[i].w - mx);
        sum += (v[i].x + v[i].y) + (v[i].z + v[i].w);
    }
#pragma unroll
    for (int o = 16; o > 0; o >>= 1)
        sum += __shfl_xor_sync(0xffffffffu, sum, o);

    float inv = 1.0f / sum;
#pragma unroll
    for (int i = 0; i < 16; ++i) {
        v[i].x *= inv; v[i].y *= inv; v[i].z *= inv; v[i].w *= inv;
        p4[lane + i * 32] = v[i];
    }
}

// ---------------------------------------------------------------------------
extern "C" void kernel_launch(void* const* d_in, const int* in_sizes, int n_in,
                              void* d_out, int out_size)
{
    const float* q    = (const float*)d_in[0];
    const float* k    = (const float*)d_in[1];
    const float* v    = (const float*)d_in[2];
    const float* wq_w = (const float*)d_in[3];
    const float* wq_b = (const float*)d_in[4];
    const float* wk_w = (const float*)d_in[5];
    const float* wk_b = (const float*)d_in[6];
    const float* wv_w = (const float*)d_in[7];
    const float* wv_b = (const float*)d_in[8];
    const float* fc_w = (const float*)d_in[9];
    const float* fc_b = (const float*)d_in[10];

    float* out  = (float*)d_out;
    float* attn = out + (size_t)BB * SS * FF;

    uint16_t *wq_h, *wq_l, *wk_h, *wk_l, *wv_h, *wv_l, *fcw_h, *fcw_l;
    uint16_t *qh_h, *qh_l, *kh_h, *kh_l, *vt_h, *vt_l, *ctx_h, *ctx_l;
    cudaGetSymbolAddress((void**)&wq_h, g_wq_h); cudaGetSymbolAddress((void**)&wq_l, g_wq_l);
    cudaGetSymbolAddress((void**)&wk_h, g_wk_h); cudaGetSymbolAddress((void**)&wk_l, g_wk_l);
    cudaGetSymbolAddress((void**)&wv_h, g_wv_h); cudaGetSymbolAddress((void**)&wv_l, g_wv_l);
    cudaGetSymbolAddress((void**)&fcw_h, g_fcw_h); cudaGetSymbolAddress((void**)&fcw_l, g_fcw_l);
    cudaGetSymbolAddress((void**)&qh_h, g_qh_h); cudaGetSymbolAddress((void**)&qh_l, g_qh_l);
    cudaGetSymbolAddress((void**)&kh_h, g_kh_h); cudaGetSymbolAddress((void**)&kh_l, g_kh_l);
    cudaGetSymbolAddress((void**)&vt_h, g_vt_h); cudaGetSymbolAddress((void**)&vt_l, g_vt_l);
    cudaGetSymbolAddress((void**)&ctx_h, g_ctx_h); cudaGetSymbolAddress((void**)&ctx_l, g_ctx_l);

    const int SM_PROJ = (128 * 40 * 2 + 128 * 40 * 2) * 2;  // 40960
    const int SM_SCOR = (128 * 72 * 2 + 128 * 72 * 2) * 2;  // 73728
    const int SM_CTX  = (128 * 40 * 2 + 64 * 40 * 2) * 2;   // 30720

    cudaFuncSetAttribute(mma_gemm<0>, cudaFuncAttributeMaxDynamicSharedMemorySize, SM_PROJ);
    cudaFuncSetAttribute(mma_gemm<1>, cudaFuncAttributeMaxDynamicSharedMemorySize, SM_PROJ);
    cudaFuncSetAttribute(mma_gemm<2>, cudaFuncAttributeMaxDynamicSharedMemorySize, SM_SCOR);
    cudaFuncSetAttribute(mma_gemm<3>, cudaFuncAttributeMaxDynamicSharedMemorySize, SM_CTX);
    cudaFuncSetAttribute(mma_gemm<4>, cudaFuncAttributeMaxDynamicSharedMemorySize, SM_PROJ);

    presplit_kernel<<<256, 256>>>((const float4*)wq_w, wq_h, wq_l);
    presplit_kernel<<<256, 256>>>((const float4*)wk_w, wk_h, wk_l);
    presplit_kernel<<<256, 256>>>((const float4*)wv_w, wv_h, wv_l);
    presplit_kernel<<<256, 256>>>((const float4*)fc_w, fcw_h, fcw_l);

    dim3 gProj(FF / 128, (BB * SS) / 128);     // (8, 64)
    mma_gemm<0><<<gProj, 128, SM_PROJ>>>(nullptr, nullptr, q, wq_h, wq_l, wq_b,
                                         nullptr, qh_h, qh_l);
    mma_gemm<0><<<gProj, 128, SM_PROJ>>>(nullptr, nullptr, k, wk_h, wk_l, wk_b,
                                         nullptr, kh_h, kh_l);
    mma_gemm<1><<<gProj, 128, SM_PROJ>>>(nullptr, nullptr, v, wv_h, wv_l, wv_b,
                                         nullptr, vt_h, vt_l);

    dim3 gS(SS / 128, SS / 128, BB * HH);      // (16, 16, 64)
    mma_gemm<2><<<gS, 128, SM_SCOR>>>(qh_h, qh_l, nullptr, kh_h, kh_l, nullptr,
                                      attn, nullptr, nullptr);

    softmax_kernel<<<(unsigned)((size_t)BB * HH * SS / 8), 256>>>(attn);

    dim3 gC(1, SS / 128, BB * HH);             // (1, 16, 64)
    mma_gemm<3><<<gC, 128, SM_CTX>>>(nullptr, nullptr, attn, vt_h, vt_l, nullptr,
                                     nullptr, ctx_h, ctx_l);

    mma_gemm<4><<<gProj, 128, SM_PROJ>>>(ctx_h, ctx_l, nullptr, fcw_h, fcw_l, fc_b,
                                         out, nullptr, nullptr);
}

// round 12
// speedup vs baseline: 1.0033x; 1.0033x over previous
#include <cuda_runtime.h>
#include <cuda_bf16.h>
#include <cstdint>

#define BB 4
#define SS 2048
#define FF 1024
#define HH 16
#define DD 64

// ---------------------------------------------------------------------------
// Scratch (allocation-free requirement -> __device__ globals)
// ---------------------------------------------------------------------------
__device__ uint16_t g_wq_h[1048576], g_wq_l[1048576];
__device__ uint16_t g_wk_h[1048576], g_wk_l[1048576];
__device__ uint16_t g_wv_h[1048576], g_wv_l[1048576];
__device__ uint16_t g_fcw_h[1048576], g_fcw_l[1048576];
__device__ uint16_t g_qh_h[16777216], g_qh_l[16777216];   // [B,H,S,D]
__device__ uint16_t g_kh_h[16777216], g_kh_l[16777216];   // [B,H,S,D]
__device__ uint16_t g_vt_h[16777216], g_vt_l[16777216];   // [B,H,D,S]
__device__ uint16_t g_ctx_h[16777216], g_ctx_l[16777216]; // [B,S,F]

// ---------------------------------------------------------------------------
__device__ __forceinline__ uint32_t smem_u32(const void* p) {
    uint32_t a;
    asm("{ .reg .u64 t; cvta.to.shared.u64 t, %1; cvt.u32.u64 %0, t; }"
        : "=r"(a) : "l"(p));
    return a;
}

__device__ __forceinline__ void ldsm4(uint32_t* r, uint32_t addr) {
    asm volatile("ldmatrix.sync.aligned.m8n8.x4.shared.b16 {%0,%1,%2,%3}, [%4];"
                 : "=r"(r[0]), "=r"(r[1]), "=r"(r[2]), "=r"(r[3]) : "r"(addr));
}

__device__ __forceinline__ void mma16816(float* c, const uint32_t* a,
                                         uint32_t b0, uint32_t b1) {
    asm volatile(
        "mma.sync.aligned.m16n8k16.row.col.f32.bf16.bf16.f32 "
        "{%0,%1,%2,%3}, {%4,%5,%6,%7}, {%8,%9}, {%0,%1,%2,%3};"
        : "+f"(c[0]), "+f"(c[1]), "+f"(c[2]), "+f"(c[3])
        : "r"(a[0]), "r"(a[1]), "r"(a[2]), "r"(a[3]), "r"(b0), "r"(b1));
}

__device__ __forceinline__ uint32_t packbf(float a, float b) {
    __nv_bfloat162 t = __floats2bfloat162_rn(a, b);
    return *reinterpret_cast<uint32_t*>(&t);
}

__device__ __forceinline__ void split_pack(float4 v, uint2& hi, uint2& lo) {
    __nv_bfloat16 hx = __float2bfloat16(v.x);
    __nv_bfloat16 hy = __float2bfloat16(v.y);
    __nv_bfloat16 hz = __float2bfloat16(v.z);
    __nv_bfloat16 hw = __float2bfloat16(v.w);
    hi.x = packbf(v.x, v.y);
    hi.y = packbf(v.z, v.w);
    lo.x = packbf(v.x - __bfloat162float(hx), v.y - __bfloat162float(hy));
    lo.y = packbf(v.z - __bfloat162float(hz), v.w - __bfloat162float(hw));
}

__device__ __forceinline__ void store_split(uint16_t* Dh, uint16_t* Dl,
                                            size_t idx, float val) {
    __nv_bfloat16 h = __float2bfloat16(val);
    *(__nv_bfloat16*)&Dh[idx] = h;
    *(__nv_bfloat16*)&Dl[idx] = __float2bfloat16(val - __bfloat162float(h));
}

// ---------------------------------------------------------------------------
__global__ __launch_bounds__(256) void presplit_kernel(
    const float4* __restrict__ W, uint16_t* __restrict__ Wh,
    uint16_t* __restrict__ Wl)
{
#pragma unroll
    for (int u = 0; u < 4; ++u) {
        int i = (blockIdx.x * 4 + u) * 256 + threadIdx.x;
        float4 v = W[i];
        uint2 hi, lo;
        split_pack(v, hi, lo);
        ((uint2*)Wh)[i] = hi;
        ((uint2*)Wl)[i] = lo;
    }
}

// ---------------------------------------------------------------------------
// 3xBF16 mma.sync NT-GEMM, 128 threads (4 warps, 2x2), 64x64 warp tiles.
//  0: proj Q/K : A f32 (split in-kernel) x presplit W -> bf16 [B,H,S,D]
//  1: proj V   : same -> transposed bf16 [B,H,D,S]
//  2: scores   : per bh: bf16 qh @ kh^T * 0.125 -> f32 logits (KC=1)
//  3: ctx      : per bh: attn f32 (split in-kernel) @ vt^T -> ctx bf16
//  4: fc       : bf16 ctx @ fcw^T + b, ReLU -> f32 out
// ---------------------------------------------------------------------------
template <int STAGE>
__global__ __launch_bounds__(128, 2) void mma_gemm(
    const uint16_t* __restrict__ Ah, const uint16_t* __restrict__ Al,
    const float*    __restrict__ Af,
    const uint16_t* __restrict__ Bh, const uint16_t* __restrict__ Bl,
    const float* __restrict__ bias,
    float* __restrict__ Df, uint16_t* __restrict__ Dh, uint16_t* __restrict__ Dl)
{
    constexpr int NT   = (STAGE == 3) ? 64 : 128;
    constexpr int BK   = (STAGE == 2) ? 64 : 32;
    constexpr int KTOT = (STAGE == 2) ? 64 : ((STAGE == 3) ? 2048 : 1024);
    constexpr int KC   = KTOT / BK;
    constexpr int LDA  = (STAGE == 2) ? 64 : ((STAGE == 3) ? 2048 : 1024);
    constexpr int LDB  = (STAGE == 2) ? 64 : ((STAGE == 3) ? 2048 : 1024);
    constexpr int PADX = (STAGE == 2) ? 72 : 40;
    constexpr int KSL  = BK / 16;
    constexpr int WN     = NT / 2;       // warp cols: 64 or 32
    constexpr int NPAIRS = WN / 16;      // 4 or 2
    constexpr int NTILES = 2 * NPAIRS;   // 8 or 4
    constexpr bool A_F32 = (STAGE <= 1) || (STAGE == 3);

    extern __shared__ __align__(16) uint16_t dsm[];
    uint16_t* sA_h = dsm;
    uint16_t* sA_l = sA_h + 128 * PADX;
    uint16_t* sB_h = sA_l + 128 * PADX;
    uint16_t* sB_l = sB_h + NT * PADX;

    const int tid  = threadIdx.x;
    const int wid  = tid >> 5;
    const int lane = tid & 31;
    const int warp_m = wid >> 1;   // 0..1  (64 rows each)
    const int warp_n = wid & 1;    // 0..1  (WN cols each)

    const int m0 = blockIdx.y * 128;
    const int n0 = blockIdx.x * NT;
    const int bh = blockIdx.z;

    if constexpr (STAGE == 2) {
        size_t ao = (size_t)bh * SS * DD + (size_t)m0 * LDA;
        size_t bo = (size_t)bh * SS * DD + (size_t)n0 * LDB;
        Ah += ao; Al += ao; Bh += bo; Bl += bo;
    } else if constexpr (STAGE == 3) {
        Af += (size_t)bh * SS * SS + (size_t)m0 * LDA;
        size_t bo = (size_t)bh * DD * SS;
        Bh += bo; Bl += bo;
    } else if constexpr (A_F32) {
        Af += (size_t)m0 * LDA;
        size_t bo = (size_t)n0 * LDB;
        Bh += bo; Bl += bo;
    } else {
        size_t ao = (size_t)m0 * LDA;
        size_t bo = (size_t)n0 * LDB;
        Ah += ao; Al += ao; Bh += bo; Bl += bo;
    }

    float acc[4][NTILES][4];
#pragma unroll
    for (int mt = 0; mt < 4; ++mt)
#pragma unroll
        for (int nt = 0; nt < NTILES; ++nt)
#pragma unroll
            for (int i = 0; i < 4; ++i) acc[mt][nt][i] = 0.f;

    for (int ch = 0; ch < KC; ++ch) {
        const int k0 = ch * BK;
        if (ch) __syncthreads();

        // ---- stage A tile ----
        if constexpr (A_F32) {
            // 128 rows x 32 f32; 128 threads -> 8 float4 each
#pragma unroll
            for (int i = 0; i < 8; ++i) {
                int f = tid + i * 128;
                int r = f >> 3, c = (f & 7) << 2;
                float4 v = *(const float4*)(Af + (size_t)r * LDA + k0 + c);
                uint2 hi, lo;
                split_pack(v, hi, lo);
                *(uint2*)&sA_h[r * PADX + c] = hi;
                *(uint2*)&sA_l[r * PADX + c] = lo;
            }
        } else {
            constexpr int U4 = BK / 8;
            constexpr int IT = 128 * U4 / 128;
#pragma unroll
            for (int i = 0; i < IT; ++i) {
                int f = tid + i * 128;
                int r = f / U4, c = (f % U4) * 8;
                *(uint4*)&sA_h[r * PADX + c] = *(const uint4*)(Ah + (size_t)r * LDA + k0 + c);
                *(uint4*)&sA_l[r * PADX + c] = *(const uint4*)(Al + (size_t)r * LDA + k0 + c);
            }
        }
        // ---- stage B tile (bf16 presplit) ----
        {
            constexpr int U4 = BK / 8;
            constexpr int IT = NT * U4 / 128;
#pragma unroll
            for (int i = 0; i < IT; ++i) {
                int f = tid + i * 128;
                int r = f / U4, c = (f % U4) * 8;
                *(uint4*)&sB_h[r * PADX + c] = *(const uint4*)(Bh + (size_t)r * LDB + k0 + c);
                *(uint4*)&sB_l[r * PADX + c] = *(const uint4*)(Bl + (size_t)r * LDB + k0 + c);
            }
        }
        __syncthreads();

#pragma unroll
        for (int ks = 0; ks < KSL; ++ks) {
            const int kcol = ks * 16 + (lane >> 4) * 8;
            uint32_t ah[4][4], al[4][4];
#pragma unroll
            for (int mt = 0; mt < 4; ++mt) {
                int row = warp_m * 64 + mt * 16 + (lane & 15);
                ldsm4(ah[mt], smem_u32(&sA_h[row * PADX + kcol]));
                ldsm4(al[mt], smem_u32(&sA_l[row * PADX + kcol]));
            }
            uint32_t bhf[NPAIRS][4], blf[NPAIRS][4];
#pragma unroll
            for (int np = 0; np < NPAIRS; ++np) {
                int nrow = warp_n * WN + np * 16 + (lane & 15);
                ldsm4(bhf[np], smem_u32(&sB_h[nrow * PADX + kcol]));
                ldsm4(blf[np], smem_u32(&sB_l[nrow * PADX + kcol]));
            }
#pragma unroll
            for (int mt = 0; mt < 4; ++mt)
#pragma unroll
                for (int np = 0; np < NPAIRS; ++np)
#pragma unroll
                    for (int sub = 0; sub < 2; ++sub)
                        mma16816(acc[mt][np * 2 + sub], ah[mt],
                                 bhf[np][sub], bhf[np][sub + 2]);
#pragma unroll
            for (int mt = 0; mt < 4; ++mt)
#pragma unroll
                for (int np = 0; np < NPAIRS; ++np)
#pragma unroll
                    for (int sub = 0; sub < 2; ++sub)
                        mma16816(acc[mt][np * 2 + sub], ah[mt],
                                 blf[np][sub], blf[np][sub + 2]);
#pragma unroll
            for (int mt = 0; mt < 4; ++mt)
#pragma unroll
                for (int np = 0; np < NPAIRS; ++np)
#pragma unroll
                    for (int sub = 0; sub < 2; ++sub)
                        mma16816(acc[mt][np * 2 + sub], al[mt],
                                 bhf[np][sub], bhf[np][sub + 2]);
        }
    }

    // ---- epilogue ----
    const int g = lane >> 2;
    const int j = (lane & 3) << 1;
    const int m_base = m0 + warp_m * 64;
    const int n_base = n0 + warp_n * WN;

#pragma unroll
    for (int mt = 0; mt < 4; ++mt) {
#pragma unroll
        for (int nt = 0; nt < NTILES; ++nt) {
#pragma unroll
            for (int e = 0; e < 4; ++e) {
                int row = m_base + mt * 16 + g + (e >> 1) * 8;
                int col = n_base + nt * 8 + j + (e & 1);
                float val = acc[mt][nt][e];
                if constexpr (STAGE == 0) {
                    val += bias[col];
                    int b = row >> 11, s = row & 2047, h = col >> 6, d = col & 63;
                    store_split(Dh, Dl, (((size_t)b * HH + h) * SS + s) * DD + d, val);
                } else if constexpr (STAGE == 1) {
                    val += bias[col];
                    int b = row >> 11, s = row & 2047, h = col >> 6, d = col & 63;
                    store_split(Dh, Dl, (((size_t)b * HH + h) * DD + d) * SS + s, val);
                } else if constexpr (STAGE == 2) {
                    Df[((size_t)bh * SS + row) * SS + col] = val * 0.125f;
                } else if constexpr (STAGE == 3) {
                    int b = bh >> 4, h = bh & 15;
                    store_split(Dh, Dl, ((size_t)b * SS + row) * FF + h * DD + col, val);
                } else {
                    val += bias[col];
                    Df[(size_t)row * FF + col] = fmaxf(val, 0.f);
                }
            }
        }
    }
}

// ---------------------------------------------------------------------------
// Warp-per-row softmax (rows of 2048). Block = 8 warps = 8 rows; no barriers.
// Each lane holds 16 float4 = 64 values in registers; single read, single write.
// ---------------------------------------------------------------------------
__global__ __launch_bounds__(256) void softmax_kernel(float* __restrict__ attn)
{
    const int warp = threadIdx.x >> 5;
    const int lane = threadIdx.x & 31;
    const size_t row = (size_t)blockIdx.x * 8 + warp;
    float4* p4 = (float4*)(attn + row * SS);

    float4 v[16];
    float mx = -1e30f;
#pragma unroll
    for (int i = 0; i < 16; ++i) {
        v[i] = p4[lane + i * 32];
        mx = fmaxf(mx, fmaxf(fmaxf(v[i].x, v[i].y), fmaxf(v[i].z, v[i].w)));
    }
#pragma unroll
    for (int o = 16; o > 0; o >>= 1)
        mx = fmaxf(mx, __shfl_xor_sync(0xffffffffu, mx, o));

    float sum = 0.f;
#pragma unroll
    for (int i = 0; i < 16; ++i) {
        v[i].x = __expf(v[i].x - mx);
        v[i].y = __expf(v[i].y - mx);
        v[i].z = __expf(v[i].z - mx);
        v[i].w = __expf(v[i].w - mx);
        sum += (v[i].x + v[i].y) + (v[i].z + v[i].w);
    }
#pragma unroll
    for (int o = 16; o > 0; o >>= 1)
        sum += __shfl_xor_sync(0xffffffffu, sum, o);

    float inv = 1.0f / sum;
#pragma unroll
    for (int i = 0; i < 16; ++i) {
        v[i].x *= inv; v[i].y *= inv; v[i].z *= inv; v[i].w *= inv;
        p4[lane + i * 32] = v[i];
    }
}

// ---------------------------------------------------------------------------
extern "C" void kernel_launch(void* const* d_in, const int* in_sizes, int n_in,
                              void* d_out, int out_size)
{
    const float* q    = (const float*)d_in[0];
    const float* k    = (const float*)d_in[1];
    const float* v    = (const float*)d_in[2];
    const float* wq_w = (const float*)d_in[3];
    const float* wq_b = (const float*)d_in[4];
    const float* wk_w = (const float*)d_in[5];
    const float* wk_b = (const float*)d_in[6];
    const float* wv_w = (const float*)d_in[7];
    const float* wv_b = (const float*)d_in[8];
    const float* fc_w = (const float*)d_in[9];
    const float* fc_b = (const float*)d_in[10];

    float* out  = (float*)d_out;
    float* attn = out + (size_t)BB * SS * FF;

    uint16_t *wq_h, *wq_l, *wk_h, *wk_l, *wv_h, *wv_l, *fcw_h, *fcw_l;
    uint16_t *qh_h, *qh_l, *kh_h, *kh_l, *vt_h, *vt_l, *ctx_h, *ctx_l;
    cudaGetSymbolAddress((void**)&wq_h, g_wq_h); cudaGetSymbolAddress((void**)&wq_l, g_wq_l);
    cudaGetSymbolAddress((void**)&wk_h, g_wk_h); cudaGetSymbolAddress((void**)&wk_l, g_wk_l);
    cudaGetSymbolAddress((void**)&wv_h, g_wv_h); cudaGetSymbolAddress((void**)&wv_l, g_wv_l);
    cudaGetSymbolAddress((void**)&fcw_h, g_fcw_h); cudaGetSymbolAddress((void**)&fcw_l, g_fcw_l);
    cudaGetSymbolAddress((void**)&qh_h, g_qh_h); cudaGetSymbolAddress((void**)&qh_l, g_qh_l);
    cudaGetSymbolAddress((void**)&kh_h, g_kh_h); cudaGetSymbolAddress((void**)&kh_l, g_kh_l);
    cudaGetSymbolAddress((void**)&vt_h, g_vt_h); cudaGetSymbolAddress((void**)&vt_l, g_vt_l);
    cudaGetSymbolAddress((void**)&ctx_h, g_ctx_h); cudaGetSymbolAddress((void**)&ctx_l, g_ctx_l);

    const int SM_PROJ = (128 * 40 * 2 + 128 * 40 * 2) * 2;  // 40960
    const int SM_SCOR = (128 * 72 * 2 + 128 * 72 * 2) * 2;  // 73728
    const int SM_CTX  = (128 * 40 * 2 + 64 * 40 * 2) * 2;   // 30720

    cudaFuncSetAttribute(mma_gemm<0>, cudaFuncAttributeMaxDynamicSharedMemorySize, SM_PROJ);
    cudaFuncSetAttribute(mma_gemm<1>, cudaFuncAttributeMaxDynamicSharedMemorySize, SM_PROJ);
    cudaFuncSetAttribute(mma_gemm<2>, cudaFuncAttributeMaxDynamicSharedMemorySize, SM_SCOR);
    cudaFuncSetAttribute(mma_gemm<3>, cudaFuncAttributeMaxDynamicSharedMemorySize, SM_CTX);
    cudaFuncSetAttribute(mma_gemm<4>, cudaFuncAttributeMaxDynamicSharedMemorySize, SM_PROJ);

    presplit_kernel<<<256, 256>>>((const float4*)wq_w, wq_h, wq_l);
    presplit_kernel<<<256, 256>>>((const float4*)wk_w, wk_h, wk_l);
    presplit_kernel<<<256, 256>>>((const float4*)wv_w, wv_h, wv_l);
    presplit_kernel<<<256, 256>>>((const float4*)fc_w, fcw_h, fcw_l);

    dim3 gProj(FF / 128, (BB * SS) / 128);     // (8, 64)
    mma_gemm<0><<<gProj, 128, SM_PROJ>>>(nullptr, nullptr, q, wq_h, wq_l, wq_b,
                                         nullptr, qh_h, qh_l);
    mma_gemm<0><<<gProj, 128, SM_PROJ>>>(nullptr, nullptr, k, wk_h, wk_l, wk_b,
                                         nullptr, kh_h, kh_l);
    mma_gemm<1><<<gProj, 128, SM_PROJ>>>(nullptr, nullptr, v, wv_h, wv_l, wv_b,
                                         nullptr, vt_h, vt_l);

    dim3 gS(SS / 128, SS / 128, BB * HH);      // (16, 16, 64)
    mma_gemm<2><<<gS, 128, SM_SCOR>>>(qh_h, qh_l, nullptr, kh_h, kh_l, nullptr,
                                      attn, nullptr, nullptr);

    softmax_kernel<<<(unsigned)((size_t)BB * HH * SS / 8), 256>>>(attn);

    dim3 gC(1, SS / 128, BB * HH);             // (1, 16, 64)
    mma_gemm<3><<<gC, 128, SM_CTX>>>(nullptr, nullptr, attn, vt_h, vt_l, nullptr,
                                     nullptr, ctx_h, ctx_l);

    mma_gemm<4><<<gProj, 128, SM_PROJ>>>(ctx_h, ctx_l, nullptr, fcw_h, fcw_l, fc_b,
                                         out, nullptr, nullptr);
}

// round 14
// speedup vs baseline: 1.1305x; 1.1267x over previous
#include <cuda_runtime.h>
#include <cuda_bf16.h>
#include <cstdint>

#define BB 4
#define SS 2048
#define FF 1024
#define HH 16
#define DD 64

// ---------------------------------------------------------------------------
// Scratch (allocation-free requirement -> __device__ globals)
// ---------------------------------------------------------------------------
__device__ uint16_t g_wq_h[1048576], g_wq_l[1048576];
__device__ uint16_t g_wk_h[1048576], g_wk_l[1048576];
__device__ uint16_t g_wv_h[1048576], g_wv_l[1048576];
__device__ uint16_t g_fcw_h[1048576], g_fcw_l[1048576];
__device__ uint16_t g_qh_h[8388608], g_qh_l[8388608];   // [B,H,S,D]
__device__ uint16_t g_kh_h[8388608], g_kh_l[8388608];   // [B,H,S,D]
__device__ uint16_t g_vt_h[8388608], g_vt_l[8388608];   // [B,H,D,S]
__device__ uint16_t g_ctx_h[8388608], g_ctx_l[8388608]; // [B,S,F]
__device__ float    g_part[BB*HH*SS*16];                // per-(row, ntile) exp sums
__device__ float    g_inv[BB*HH*SS];                    // per-row 1/sum

// ---------------------------------------------------------------------------
__device__ __forceinline__ uint32_t smem_u32(const void* p) {
    uint32_t a;
    asm("{ .reg .u64 t; cvta.to.shared.u64 t, %1; cvt.u32.u64 %0, t; }"
        : "=r"(a) : "l"(p));
    return a;
}

__device__ __forceinline__ void ldsm4(uint32_t* r, uint32_t addr) {
    asm volatile("ldmatrix.sync.aligned.m8n8.x4.shared.b16 {%0,%1,%2,%3}, [%4];"
                 : "=r"(r[0]), "=r"(r[1]), "=r"(r[2]), "=r"(r[3]) : "r"(addr));
}

__device__ __forceinline__ void mma16816(float* c, const uint32_t* a,
                                         uint32_t b0, uint32_t b1) {
    asm volatile(
        "mma.sync.aligned.m16n8k16.row.col.f32.bf16.bf16.f32 "
        "{%0,%1,%2,%3}, {%4,%5,%6,%7}, {%8,%9}, {%0,%1,%2,%3};"
        : "+f"(c[0]), "+f"(c[1]), "+f"(c[2]), "+f"(c[3])
        : "r"(a[0]), "r"(a[1]), "r"(a[2]), "r"(a[3]), "r"(b0), "r"(b1));
}

__device__ __forceinline__ uint32_t packbf(float a, float b) {
    __nv_bfloat162 t = __floats2bfloat162_rn(a, b);
    return *reinterpret_cast<uint32_t*>(&t);
}

__device__ __forceinline__ void split_pack(float4 v, uint2& hi, uint2& lo) {
    __nv_bfloat16 hx = __float2bfloat16(v.x);
    __nv_bfloat16 hy = __float2bfloat16(v.y);
    __nv_bfloat16 hz = __float2bfloat16(v.z);
    __nv_bfloat16 hw = __float2bfloat16(v.w);
    hi.x = packbf(v.x, v.y);
    hi.y = packbf(v.z, v.w);
    lo.x = packbf(v.x - __bfloat162float(hx), v.y - __bfloat162float(hy));
    lo.y = packbf(v.z - __bfloat162float(hz), v.w - __bfloat162float(hw));
}

__device__ __forceinline__ void store_split(uint16_t* Dh, uint16_t* Dl,
                                            size_t idx, float val) {
    __nv_bfloat16 h = __float2bfloat16(val);
    *(__nv_bfloat16*)&Dh[idx] = h;
    *(__nv_bfloat16*)&Dl[idx] = __float2bfloat16(val - __bfloat162float(h));
}

// ---------------------------------------------------------------------------
__global__ __launch_bounds__(256) void presplit_kernel(
    const float4* __restrict__ W, uint16_t* __restrict__ Wh,
    uint16_t* __restrict__ Wl)
{
#pragma unroll
    for (int u = 0; u < 4; ++u) {
        int i = (blockIdx.x * 4 + u) * 256 + threadIdx.x;
        float4 v = W[i];
        uint2 hi, lo;
        split_pack(v, hi, lo);
        ((uint2*)Wh)[i] = hi;
        ((uint2*)Wl)[i] = lo;
    }
}

// ---------------------------------------------------------------------------
// Reduce 16 partial sums per row -> reciprocal.
// ---------------------------------------------------------------------------
__global__ __launch_bounds__(256) void rowinv_kernel(
    const float* __restrict__ part, float* __restrict__ inv)
{
    int r = blockIdx.x * 256 + threadIdx.x;
    const float4* p = (const float4*)(part + (size_t)r * 16);
    float4 a = p[0], b = p[1], c = p[2], d = p[3];
    float s = ((a.x + a.y) + (a.z + a.w)) + ((b.x + b.y) + (b.z + b.w))
            + ((c.x + c.y) + (c.z + c.w)) + ((d.x + d.y) + (d.z + d.w));
    inv[r] = 1.0f / s;
}

// ---------------------------------------------------------------------------
template <int ROWS, int BK, int PADX>
__device__ __forceinline__ void load_bf16_tile(
    uint16_t* dh, uint16_t* dl, const uint16_t* sh, const uint16_t* sl,
    int ld, int k0, int tid)
{
    constexpr int U4 = BK / 8;
    constexpr int IT = ROWS * U4 / 256;
#pragma unroll
    for (int i = 0; i < IT; ++i) {
        int f = tid + i * 256;
        int r = f / U4, c = (f % U4) * 8;
        *(uint4*)&dh[r * PADX + c] = *(const uint4*)(sh + (size_t)r * ld + k0 + c);
        *(uint4*)&dl[r * PADX + c] = *(const uint4*)(sl + (size_t)r * ld + k0 + c);
    }
}

// ---------------------------------------------------------------------------
// 3xBF16 mma.sync NT-GEMM.  STAGE:
//  0: proj Q/K : A f32 (split in-kernel) x presplit W -> split-head bf16
//  1: proj V   : same -> transposed bf16 [B,H,D,S]
//  2: scores   : bf16 qh @ kh^T; epilogue: exp(logit/8) -> attn + row partials
//  3: ctx      : exp-probs f32 * inv (normalize, write back, split) @ vt^T
//  4: fc       : bf16 ctx @ fcw^T + b, ReLU -> f32 out
// ---------------------------------------------------------------------------
template <int STAGE>
__global__ __launch_bounds__(256, 2) void mma_gemm(
    const uint16_t* __restrict__ Ah, const uint16_t* __restrict__ Al,
    const float*    __restrict__ Af,
    const uint16_t* __restrict__ Bh, const uint16_t* __restrict__ Bl,
    const float* __restrict__ bias,
    float* __restrict__ Df, uint16_t* __restrict__ Dh, uint16_t* __restrict__ Dl,
    float* __restrict__ aux, const float* __restrict__ invg)
{
    constexpr int NT   = (STAGE == 3) ? 64 : 128;
    constexpr int BK   = (STAGE == 2) ? 64 : 32;
    constexpr int KTOT = (STAGE == 2) ? 64 : ((STAGE == 3) ? 2048 : 1024);
    constexpr int KC   = KTOT / BK;
    constexpr int LDA  = (STAGE == 2) ? 64 : ((STAGE == 3) ? 2048 : 1024);
    constexpr int LDB  = (STAGE == 2) ? 64 : ((STAGE == 3) ? 2048 : 1024);
    constexpr int PADX = (STAGE == 2) ? 72 : 40;
    constexpr int KSL  = BK / 16;
    constexpr int WN     = NT / 2;
    constexpr int NPAIRS = WN / 16;
    constexpr int NTILES = 2 * NPAIRS;
    constexpr bool A_F32 = (STAGE <= 1) || (STAGE == 3);

    extern __shared__ __align__(16) uint16_t dsm[];
    uint16_t* sA_h = dsm;
    uint16_t* sA_l = sA_h + 128 * PADX;
    uint16_t* sB_h = sA_l + 128 * PADX;
    uint16_t* sB_l = sB_h + NT * PADX;

    __shared__ float s_ps[128][2];   // stage 2: per-row partial sums (per warp_n)
    __shared__ float s_inv[128];     // stage 3: per-row 1/sum

    const int tid  = threadIdx.x;
    const int wid  = tid >> 5;
    const int lane = tid & 31;
    const int warp_m = wid >> 1;
    const int warp_n = wid & 1;

    const int m0 = blockIdx.y * 128;
    const int n0 = blockIdx.x * NT;
    const int bh = blockIdx.z;

    if constexpr (STAGE == 2) {
        size_t ao = (size_t)bh * SS * DD + (size_t)m0 * LDA;
        size_t bo = (size_t)bh * SS * DD + (size_t)n0 * LDB;
        Ah += ao; Al += ao; Bh += bo; Bl += bo;
    } else if constexpr (STAGE == 3) {
        size_t ao = (size_t)bh * SS * SS + (size_t)m0 * LDA;
        Af += ao; Df += ao;            // Df aliases attn for normalized writeback
        size_t bo = (size_t)bh * DD * SS;
        Bh += bo; Bl += bo;
    } else if constexpr (A_F32) {
        Af += (size_t)m0 * LDA;
        size_t bo = (size_t)n0 * LDB;
        Bh += bo; Bl += bo;
    } else {
        size_t ao = (size_t)m0 * LDA;
        size_t bo = (size_t)n0 * LDB;
        Ah += ao; Al += ao; Bh += bo; Bl += bo;
    }

    if constexpr (STAGE == 3) {
        if (tid < 128) s_inv[tid] = invg[(size_t)bh * SS + m0 + tid];
        __syncthreads();
    }

    float acc[2][NTILES][4];
#pragma unroll
    for (int mt = 0; mt < 2; ++mt)
#pragma unroll
        for (int nt = 0; nt < NTILES; ++nt)
#pragma unroll
            for (int i = 0; i < 4; ++i) acc[mt][nt][i] = 0.f;

    for (int ch = 0; ch < KC; ++ch) {
        const int k0 = ch * BK;
        if (ch) __syncthreads();

        if constexpr (A_F32) {
#pragma unroll
            for (int i = 0; i < 4; ++i) {
                int f = tid + i * 256;
                int r = f >> 3, c = (f & 7) << 2;
                float4 v = *(const float4*)(Af + (size_t)r * LDA + k0 + c);
                if constexpr (STAGE == 3) {
                    float iv = s_inv[r];
                    v.x *= iv; v.y *= iv; v.z *= iv; v.w *= iv;
                    *(float4*)(Df + (size_t)r * LDA + k0 + c) = v;  // normalized attn
                }
                uint2 hi, lo;
                split_pack(v, hi, lo);
                *(uint2*)&sA_h[r * PADX + c] = hi;
                *(uint2*)&sA_l[r * PADX + c] = lo;
            }
        } else {
            load_bf16_tile<128, BK, PADX>(sA_h, sA_l, Ah, Al, LDA, k0, tid);
        }
        load_bf16_tile<NT, BK, PADX>(sB_h, sB_l, Bh, Bl, LDB, k0, tid);
        __syncthreads();

#pragma unroll
        for (int ks = 0; ks < KSL; ++ks) {
            const int kcol = ks * 16 + (lane >> 4) * 8;
            uint32_t ah[2][4], al[2][4];
#pragma unroll
            for (int mt = 0; mt < 2; ++mt) {
                int row = warp_m * 32 + mt * 16 + (lane & 15);
                ldsm4(ah[mt], smem_u32(&sA_h[row * PADX + kcol]));
                ldsm4(al[mt], smem_u32(&sA_l[row * PADX + kcol]));
            }
            uint32_t bhf[NPAIRS][4], blf[NPAIRS][4];
#pragma unroll
            for (int np = 0; np < NPAIRS; ++np) {
                int nrow = warp_n * WN + np * 16 + (lane & 15);
                ldsm4(bhf[np], smem_u32(&sB_h[nrow * PADX + kcol]));
                ldsm4(blf[np], smem_u32(&sB_l[nrow * PADX + kcol]));
            }
#pragma unroll
            for (int mt = 0; mt < 2; ++mt)
#pragma unroll
                for (int np = 0; np < NPAIRS; ++np)
#pragma unroll
                    for (int sub = 0; sub < 2; ++sub)
                        mma16816(acc[mt][np * 2 + sub], ah[mt],
                                 bhf[np][sub], bhf[np][sub + 2]);
#pragma unroll
            for (int mt = 0; mt < 2; ++mt)
#pragma unroll
                for (int np = 0; np < NPAIRS; ++np)
#pragma unroll
                    for (int sub = 0; sub < 2; ++sub)
                        mma16816(acc[mt][np * 2 + sub], ah[mt],
                                 blf[np][sub], blf[np][sub + 2]);
#pragma unroll
            for (int mt = 0; mt < 2; ++mt)
#pragma unroll
                for (int np = 0; np < NPAIRS; ++np)
#pragma unroll
                    for (int sub = 0; sub < 2; ++sub)
                        mma16816(acc[mt][np * 2 + sub], al[mt],
                                 bhf[np][sub], bhf[np][sub + 2]);
        }
    }

    // ---- epilogue ----
    const int g = lane >> 2;
    const int j = (lane & 3) << 1;
    const int m_base = m0 + warp_m * 32;
    const int n_base = n0 + warp_n * WN;

    if constexpr (STAGE == 2) {
        // exp, write attn, accumulate row partial sums (deterministic)
        float rsum[2][2] = {{0.f, 0.f}, {0.f, 0.f}};
#pragma unroll
        for (int mt = 0; mt < 2; ++mt) {
#pragma unroll
            for (int nt = 0; nt < NTILES; ++nt) {
#pragma unroll
                for (int e = 0; e < 4; ++e) {
                    int row = m_base + mt * 16 + g + (e >> 1) * 8;
                    int col = n_base + nt * 8 + j + (e & 1);
                    float ev = __expf(acc[mt][nt][e] * 0.125f);
                    Df[((size_t)bh * SS + row) * SS + col] = ev;
                    rsum[mt][e >> 1] += ev;
                }
            }
        }
#pragma unroll
        for (int mt = 0; mt < 2; ++mt) {
#pragma unroll
            for (int h = 0; h < 2; ++h) {
                float r = rsum[mt][h];
                r += __shfl_xor_sync(0xffffffffu, r, 1);
                r += __shfl_xor_sync(0xffffffffu, r, 2);
                if ((lane & 3) == 0) {
                    int lrow = warp_m * 32 + mt * 16 + g + h * 8;
                    s_ps[lrow][warp_n] = r;
                }
            }
        }
        __syncthreads();
        if (tid < 128) {
            aux[((size_t)bh * SS + m0 + tid) * 16 + blockIdx.x] =
                s_ps[tid][0] + s_ps[tid][1];
        }
    } else {
#pragma unroll
        for (int mt = 0; mt < 2; ++mt) {
#pragma unroll
            for (int nt = 0; nt < NTILES; ++nt) {
#pragma unroll
                for (int e = 0; e < 4; ++e) {
                    int row = m_base + mt * 16 + g + (e >> 1) * 8;
                    int col = n_base + nt * 8 + j + (e & 1);
                    float val = acc[mt][nt][e];
                    if constexpr (STAGE == 0) {
                        val += bias[col];
                        int b = row >> 11, s = row & 2047, h = col >> 6, d = col & 63;
                        store_split(Dh, Dl, (((size_t)b * HH + h) * SS + s) * DD + d, val);
                    } else if constexpr (STAGE == 1) {
                        val += bias[col];
                        int b = row >> 11, s = row & 2047, h = col >> 6, d = col & 63;
                        store_split(Dh, Dl, (((size_t)b * HH + h) * DD + d) * SS + s, val);
                    } else if constexpr (STAGE == 3) {
                        // row IS the global sequence index within this (b,h)
                        int b = bh >> 4, h = bh & 15;
                        store_split(Dh, Dl,
                                    ((size_t)b * SS + row) * FF + h * DD + col, val);
                    } else {
                        val += bias[col];
                        Df[(size_t)row * FF + col] = fmaxf(val, 0.f);
                    }
                }
            }
        }
    }
}

// ---------------------------------------------------------------------------
extern "C" void kernel_launch(void* const* d_in, const int* in_sizes, int n_in,
                              void* d_out, int out_size)
{
    const float* q    = (const float*)d_in[0];
    const float* k    = (const float*)d_in[1];
    const float* v    = (const float*)d_in[2];
    const float* wq_w = (const float*)d_in[3];
    const float* wq_b = (const float*)d_in[4];
    const float* wk_w = (const float*)d_in[5];
    const float* wk_b = (const float*)d_in[6];
    const float* wv_w = (const float*)d_in[7];
    const float* wv_b = (const float*)d_in[8];
    const float* fc_w = (const float*)d_in[9];
    const float* fc_b = (const float*)d_in[10];

    float* out  = (float*)d_out;
    float* attn = out + (size_t)BB * SS * FF;

    uint16_t *wq_h, *wq_l, *wk_h, *wk_l, *wv_h, *wv_l, *fcw_h, *fcw_l;
    uint16_t *qh_h, *qh_l, *kh_h, *kh_l, *vt_h, *vt_l, *ctx_h, *ctx_l;
    float *part, *inv;
    cudaGetSymbolAddress((void**)&wq_h, g_wq_h); cudaGetSymbolAddress((void**)&wq_l, g_wq_l);
    cudaGetSymbolAddress((void**)&wk_h, g_wk_h); cudaGetSymbolAddress((void**)&wk_l, g_wk_l);
    cudaGetSymbolAddress((void**)&wv_h, g_wv_h); cudaGetSymbolAddress((void**)&wv_l, g_wv_l);
    cudaGetSymbolAddress((void**)&fcw_h, g_fcw_h); cudaGetSymbolAddress((void**)&fcw_l, g_fcw_l);
    cudaGetSymbolAddress((void**)&qh_h, g_qh_h); cudaGetSymbolAddress((void**)&qh_l, g_qh_l);
    cudaGetSymbolAddress((void**)&kh_h, g_kh_h); cudaGetSymbolAddress((void**)&kh_l, g_kh_l);
    cudaGetSymbolAddress((void**)&vt_h, g_vt_h); cudaGetSymbolAddress((void**)&vt_l, g_vt_l);
    cudaGetSymbolAddress((void**)&ctx_h, g_ctx_h); cudaGetSymbolAddress((void**)&ctx_l, g_ctx_l);
    cudaGetSymbolAddress((void**)&part, g_part);  cudaGetSymbolAddress((void**)&inv, g_inv);

    const int SM_PROJ = (128 * 40 * 2 + 128 * 40 * 2) * 2;  // 40960
    const int SM_SCOR = (128 * 72 * 2 + 128 * 72 * 2) * 2;  // 73728
    const int SM_CTX  = (128 * 40 * 2 + 64 * 40 * 2) * 2;   // 30720

    cudaFuncSetAttribute(mma_gemm<0>, cudaFuncAttributeMaxDynamicSharedMemorySize, SM_PROJ);
    cudaFuncSetAttribute(mma_gemm<1>, cudaFuncAttributeMaxDynamicSharedMemorySize, SM_PROJ);
    cudaFuncSetAttribute(mma_gemm<2>, cudaFuncAttributeMaxDynamicSharedMemorySize, SM_SCOR);
    cudaFuncSetAttribute(mma_gemm<3>, cudaFuncAttributeMaxDynamicSharedMemorySize, SM_CTX);
    cudaFuncSetAttribute(mma_gemm<4>, cudaFuncAttributeMaxDynamicSharedMemorySize, SM_PROJ);

    presplit_kernel<<<256, 256>>>((const float4*)wq_w, wq_h, wq_l);
    presplit_kernel<<<256, 256>>>((const float4*)wk_w, wk_h, wk_l);
    presplit_kernel<<<256, 256>>>((const float4*)wv_w, wv_h, wv_l);
    presplit_kernel<<<256, 256>>>((const float4*)fc_w, fcw_h, fcw_l);

    dim3 gProj(FF / 128, (BB * SS) / 128);     // (8, 64)
    mma_gemm<0><<<gProj, 256, SM_PROJ>>>(nullptr, nullptr, q, wq_h, wq_l, wq_b,
                                         nullptr, qh_h, qh_l, nullptr, nullptr);
    mma_gemm<0><<<gProj, 256, SM_PROJ>>>(nullptr, nullptr, k, wk_h, wk_l, wk_b,
                                         nullptr, kh_h, kh_l, nullptr, nullptr);
    mma_gemm<1><<<gProj, 256, SM_PROJ>>>(nullptr, nullptr, v, wv_h, wv_l, wv_b,
                                         nullptr, vt_h, vt_l, nullptr, nullptr);

    dim3 gS(SS / 128, SS / 128, BB * HH);      // (16, 16, 64)
    mma_gemm<2><<<gS, 256, SM_SCOR>>>(qh_h, qh_l, nullptr, kh_h, kh_l, nullptr,
                                      attn, nullptr, nullptr, part, nullptr);

    rowinv_kernel<<<BB * HH * SS / 256, 256>>>(part, inv);

    dim3 gC(1, SS / 128, BB * HH);             // (1, 16, 64)
    mma_gemm<3><<<gC, 256, SM_CTX>>>(nullptr, nullptr, attn, vt_h, vt_l, nullptr,
                                     attn, ctx_h, ctx_l, nullptr, inv);

    mma_gemm<4><<<gProj, 256, SM_PROJ>>>(ctx_h, ctx_l, nullptr, fcw_h, fcw_l, fc_b,
                                         out, nullptr, nullptr, nullptr, nullptr);
}

// round 15
// speedup vs baseline: 1.1311x; 1.0006x over previous
#include <cuda_runtime.h>
#include <cuda_bf16.h>
#include <cstdint>

#define BB 4
#define SS 2048
#define FF 1024
#define HH 16
#define DD 64

// ---------------------------------------------------------------------------
// Scratch (allocation-free requirement -> __device__ globals)
// ---------------------------------------------------------------------------
__device__ uint16_t g_wq_h[1048576], g_wq_l[1048576];
__device__ uint16_t g_wk_h[1048576], g_wk_l[1048576];
__device__ uint16_t g_wv_h[1048576], g_wv_l[1048576];
__device__ uint16_t g_fcw_h[1048576], g_fcw_l[1048576];
__device__ uint16_t g_qh_h[8388608], g_qh_l[8388608];   // [B,H,S,D]
__device__ uint16_t g_kh_h[8388608], g_kh_l[8388608];   // [B,H,S,D]
__device__ uint16_t g_vt_h[8388608], g_vt_l[8388608];   // [B,H,D,S]
__device__ uint16_t g_ctx_h[8388608], g_ctx_l[8388608]; // [B,S,F]
__device__ float    g_part[BB*HH*SS*16];                // per-(row, ntile) exp sums
__device__ float    g_inv[BB*HH*SS];                    // per-row 1/sum

// ---------------------------------------------------------------------------
__device__ __forceinline__ uint32_t smem_u32(const void* p) {
    uint32_t a;
    asm("{ .reg .u64 t; cvta.to.shared.u64 t, %1; cvt.u32.u64 %0, t; }"
        : "=r"(a) : "l"(p));
    return a;
}

__device__ __forceinline__ void ldsm4(uint32_t* r, uint32_t addr) {
    asm volatile("ldmatrix.sync.aligned.m8n8.x4.shared.b16 {%0,%1,%2,%3}, [%4];"
                 : "=r"(r[0]), "=r"(r[1]), "=r"(r[2]), "=r"(r[3]) : "r"(addr));
}

__device__ __forceinline__ void mma16816(float* c, const uint32_t* a,
                                         uint32_t b0, uint32_t b1) {
    asm volatile(
        "mma.sync.aligned.m16n8k16.row.col.f32.bf16.bf16.f32 "
        "{%0,%1,%2,%3}, {%4,%5,%6,%7}, {%8,%9}, {%0,%1,%2,%3};"
        : "+f"(c[0]), "+f"(c[1]), "+f"(c[2]), "+f"(c[3])
        : "r"(a[0]), "r"(a[1]), "r"(a[2]), "r"(a[3]), "r"(b0), "r"(b1));
}

__device__ __forceinline__ uint32_t packbf(float a, float b) {
    __nv_bfloat162 t = __floats2bfloat162_rn(a, b);
    return *reinterpret_cast<uint32_t*>(&t);
}

__device__ __forceinline__ void split_pack(float4 v, uint2& hi, uint2& lo) {
    __nv_bfloat16 hx = __float2bfloat16(v.x);
    __nv_bfloat16 hy = __float2bfloat16(v.y);
    __nv_bfloat16 hz = __float2bfloat16(v.z);
    __nv_bfloat16 hw = __float2bfloat16(v.w);
    hi.x = packbf(v.x, v.y);
    hi.y = packbf(v.z, v.w);
    lo.x = packbf(v.x - __bfloat162float(hx), v.y - __bfloat162float(hy));
    lo.y = packbf(v.z - __bfloat162float(hz), v.w - __bfloat162float(hw));
}

__device__ __forceinline__ void store_split(uint16_t* Dh, uint16_t* Dl,
                                            size_t idx, float val) {
    __nv_bfloat16 h = __float2bfloat16(val);
    *(__nv_bfloat16*)&Dh[idx] = h;
    *(__nv_bfloat16*)&Dl[idx] = __float2bfloat16(val - __bfloat162float(h));
}

// ---------------------------------------------------------------------------
__global__ __launch_bounds__(256) void presplit_kernel(
    const float4* __restrict__ W, uint16_t* __restrict__ Wh,
    uint16_t* __restrict__ Wl)
{
#pragma unroll
    for (int u = 0; u < 4; ++u) {
        int i = (blockIdx.x * 4 + u) * 256 + threadIdx.x;
        float4 v = W[i];
        uint2 hi, lo;
        split_pack(v, hi, lo);
        ((uint2*)Wh)[i] = hi;
        ((uint2*)Wl)[i] = lo;
    }
}

// ---------------------------------------------------------------------------
// Reduce 16 partial sums per row -> reciprocal.
// ---------------------------------------------------------------------------
__global__ __launch_bounds__(256) void rowinv_kernel(
    const float* __restrict__ part, float* __restrict__ inv)
{
    int r = blockIdx.x * 256 + threadIdx.x;
    const float4* p = (const float4*)(part + (size_t)r * 16);
    float4 a = p[0], b = p[1], c = p[2], d = p[3];
    float s = ((a.x + a.y) + (a.z + a.w)) + ((b.x + b.y) + (b.z + b.w))
            + ((c.x + c.y) + (c.z + c.w)) + ((d.x + d.y) + (d.z + d.w));
    inv[r] = 1.0f / s;
}

// ---------------------------------------------------------------------------
template <int ROWS, int BK, int PADX>
__device__ __forceinline__ void load_bf16_tile(
    uint16_t* dh, uint16_t* dl, const uint16_t* sh, const uint16_t* sl,
    int ld, int k0, int tid)
{
    constexpr int U4 = BK / 8;
    constexpr int IT = ROWS * U4 / 256;
#pragma unroll
    for (int i = 0; i < IT; ++i) {
        int f = tid + i * 256;
        int r = f / U4, c = (f % U4) * 8;
        *(uint4*)&dh[r * PADX + c] = *(const uint4*)(sh + (size_t)r * ld + k0 + c);
        *(uint4*)&dl[r * PADX + c] = *(const uint4*)(sl + (size_t)r * ld + k0 + c);
    }
}

// ---------------------------------------------------------------------------
// 3xBF16 mma.sync NT-GEMM.  STAGE:
//  0: proj Q/K : A f32 (split in-kernel) x presplit W -> split-head bf16
//  1: proj V   : same -> transposed bf16 [B,H,D,S]
//  2: scores   : bf16 qh @ kh^T; epilogue: exp(logit/8) -> attn + row partials
//  3: ctx      : exp-probs f32 * inv (normalize, write back, split) @ vt^T
//  4: fc       : bf16 ctx @ fcw^T + b, ReLU -> f32 out
// ---------------------------------------------------------------------------
template <int STAGE>
__global__ __launch_bounds__(256, 2) void mma_gemm(
    const uint16_t* __restrict__ Ah, const uint16_t* __restrict__ Al,
    const float*    __restrict__ Af,
    const uint16_t* __restrict__ Bh, const uint16_t* __restrict__ Bl,
    const float* __restrict__ bias,
    float* __restrict__ Df, uint16_t* __restrict__ Dh, uint16_t* __restrict__ Dl,
    float* __restrict__ aux, const float* __restrict__ invg)
{
    constexpr int NT   = (STAGE == 3) ? 64 : 128;
    constexpr int BK   = (STAGE == 2) ? 64 : 32;
    constexpr int KTOT = (STAGE == 2) ? 64 : ((STAGE == 3) ? 2048 : 1024);
    constexpr int KC   = KTOT / BK;
    constexpr int LDA  = (STAGE == 2) ? 64 : ((STAGE == 3) ? 2048 : 1024);
    constexpr int LDB  = (STAGE == 2) ? 64 : ((STAGE == 3) ? 2048 : 1024);
    constexpr int PADX = (STAGE == 2) ? 72 : 40;
    constexpr int KSL  = BK / 16;
    constexpr int WN     = NT / 2;
    constexpr int NPAIRS = WN / 16;
    constexpr int NTILES = 2 * NPAIRS;
    constexpr bool A_F32 = (STAGE <= 1) || (STAGE == 3);

    extern __shared__ __align__(16) uint16_t dsm[];
    uint16_t* sA_h = dsm;
    uint16_t* sA_l = sA_h + 128 * PADX;
    uint16_t* sB_h = sA_l + 128 * PADX;
    uint16_t* sB_l = sB_h + NT * PADX;

    __shared__ float s_ps[128][2];   // stage 2: per-row partial sums (per warp_n)
    __shared__ float s_inv[128];     // stage 3: per-row 1/sum

    const int tid  = threadIdx.x;
    const int wid  = tid >> 5;
    const int lane = tid & 31;
    const int warp_m = wid >> 1;
    const int warp_n = wid & 1;

    const int m0 = blockIdx.y * 128;
    const int n0 = blockIdx.x * NT;
    const int bh = blockIdx.z;

    if constexpr (STAGE == 2) {
        size_t ao = (size_t)bh * SS * DD + (size_t)m0 * LDA;
        size_t bo = (size_t)bh * SS * DD + (size_t)n0 * LDB;
        Ah += ao; Al += ao; Bh += bo; Bl += bo;
    } else if constexpr (STAGE == 3) {
        size_t ao = (size_t)bh * SS * SS + (size_t)m0 * LDA;
        Af += ao; Df += ao;            // Df aliases attn for normalized writeback
        size_t bo = (size_t)bh * DD * SS;
        Bh += bo; Bl += bo;
    } else if constexpr (A_F32) {
        Af += (size_t)m0 * LDA;
        size_t bo = (size_t)n0 * LDB;
        Bh += bo; Bl += bo;
    } else {
        size_t ao = (size_t)m0 * LDA;
        size_t bo = (size_t)n0 * LDB;
        Ah += ao; Al += ao; Bh += bo; Bl += bo;
    }

    if constexpr (STAGE == 3) {
        if (tid < 128) s_inv[tid] = invg[(size_t)bh * SS + m0 + tid];
        __syncthreads();
    }

    float acc[2][NTILES][4];
#pragma unroll
    for (int mt = 0; mt < 2; ++mt)
#pragma unroll
        for (int nt = 0; nt < NTILES; ++nt)
#pragma unroll
            for (int i = 0; i < 4; ++i) acc[mt][nt][i] = 0.f;

    for (int ch = 0; ch < KC; ++ch) {
        const int k0 = ch * BK;
        if (ch) __syncthreads();

        if constexpr (A_F32) {
#pragma unroll
            for (int i = 0; i < 4; ++i) {
                int f = tid + i * 256;
                int r = f >> 3, c = (f & 7) << 2;
                float4 v = *(const float4*)(Af + (size_t)r * LDA + k0 + c);
                if constexpr (STAGE == 3) {
                    float iv = s_inv[r];
                    v.x *= iv; v.y *= iv; v.z *= iv; v.w *= iv;
                    *(float4*)(Df + (size_t)r * LDA + k0 + c) = v;  // normalized attn
                }
                uint2 hi, lo;
                split_pack(v, hi, lo);
                *(uint2*)&sA_h[r * PADX + c] = hi;
                *(uint2*)&sA_l[r * PADX + c] = lo;
            }
        } else {
            load_bf16_tile<128, BK, PADX>(sA_h, sA_l, Ah, Al, LDA, k0, tid);
        }
        load_bf16_tile<NT, BK, PADX>(sB_h, sB_l, Bh, Bl, LDB, k0, tid);
        __syncthreads();

#pragma unroll
        for (int ks = 0; ks < KSL; ++ks) {
            const int kcol = ks * 16 + (lane >> 4) * 8;
            uint32_t ah[2][4], al[2][4];
#pragma unroll
            for (int mt = 0; mt < 2; ++mt) {
                int row = warp_m * 32 + mt * 16 + (lane & 15);
                ldsm4(ah[mt], smem_u32(&sA_h[row * PADX + kcol]));
                ldsm4(al[mt], smem_u32(&sA_l[row * PADX + kcol]));
            }
            uint32_t bhf[NPAIRS][4], blf[NPAIRS][4];
#pragma unroll
            for (int np = 0; np < NPAIRS; ++np) {
                int nrow = warp_n * WN + np * 16 + (lane & 15);
                ldsm4(bhf[np], smem_u32(&sB_h[nrow * PADX + kcol]));
                ldsm4(blf[np], smem_u32(&sB_l[nrow * PADX + kcol]));
            }
#pragma unroll
            for (int mt = 0; mt < 2; ++mt)
#pragma unroll
                for (int np = 0; np < NPAIRS; ++np)
#pragma unroll
                    for (int sub = 0; sub < 2; ++sub)
                        mma16816(acc[mt][np * 2 + sub], ah[mt],
                                 bhf[np][sub], bhf[np][sub + 2]);
#pragma unroll
            for (int mt = 0; mt < 2; ++mt)
#pragma unroll
                for (int np = 0; np < NPAIRS; ++np)
#pragma unroll
                    for (int sub = 0; sub < 2; ++sub)
                        mma16816(acc[mt][np * 2 + sub], ah[mt],
                                 blf[np][sub], blf[np][sub + 2]);
#pragma unroll
            for (int mt = 0; mt < 2; ++mt)
#pragma unroll
                for (int np = 0; np < NPAIRS; ++np)
#pragma unroll
                    for (int sub = 0; sub < 2; ++sub)
                        mma16816(acc[mt][np * 2 + sub], al[mt],
                                 bhf[np][sub], bhf[np][sub + 2]);
        }
    }

    // ---- epilogue ----
    const int g = lane >> 2;
    const int j = (lane & 3) << 1;
    const int m_base = m0 + warp_m * 32;
    const int n_base = n0 + warp_n * WN;

    if constexpr (STAGE == 2) {
        // exp, write attn, accumulate row partial sums (deterministic)
        float rsum[2][2] = {{0.f, 0.f}, {0.f, 0.f}};
#pragma unroll
        for (int mt = 0; mt < 2; ++mt) {
#pragma unroll
            for (int nt = 0; nt < NTILES; ++nt) {
#pragma unroll
                for (int e = 0; e < 4; ++e) {
                    int row = m_base + mt * 16 + g + (e >> 1) * 8;
                    int col = n_base + nt * 8 + j + (e & 1);
                    float ev = __expf(acc[mt][nt][e] * 0.125f);
                    Df[((size_t)bh * SS + row) * SS + col] = ev;
                    rsum[mt][e >> 1] += ev;
                }
            }
        }
#pragma unroll
        for (int mt = 0; mt < 2; ++mt) {
#pragma unroll
            for (int h = 0; h < 2; ++h) {
                float r = rsum[mt][h];
                r += __shfl_xor_sync(0xffffffffu, r, 1);
                r += __shfl_xor_sync(0xffffffffu, r, 2);
                if ((lane & 3) == 0) {
                    int lrow = warp_m * 32 + mt * 16 + g + h * 8;
                    s_ps[lrow][warp_n] = r;
                }
            }
        }
        __syncthreads();
        if (tid < 128) {
            aux[((size_t)bh * SS + m0 + tid) * 16 + blockIdx.x] =
                s_ps[tid][0] + s_ps[tid][1];
        }
    } else {
#pragma unroll
        for (int mt = 0; mt < 2; ++mt) {
#pragma unroll
            for (int nt = 0; nt < NTILES; ++nt) {
#pragma unroll
                for (int e = 0; e < 4; ++e) {
                    int row = m_base + mt * 16 + g + (e >> 1) * 8;
                    int col = n_base + nt * 8 + j + (e & 1);
                    float val = acc[mt][nt][e];
                    if constexpr (STAGE == 0) {
                        val += bias[col];
                        int b = row >> 11, s = row & 2047, h = col >> 6, d = col & 63;
                        store_split(Dh, Dl, (((size_t)b * HH + h) * SS + s) * DD + d, val);
                    } else if constexpr (STAGE == 1) {
                        val += bias[col];
                        int b = row >> 11, s = row & 2047, h = col >> 6, d = col & 63;
                        store_split(Dh, Dl, (((size_t)b * HH + h) * DD + d) * SS + s, val);
                    } else if constexpr (STAGE == 3) {
                        // row IS the global sequence index within this (b,h)
                        int b = bh >> 4, h = bh & 15;
                        store_split(Dh, Dl,
                                    ((size_t)b * SS + row) * FF + h * DD + col, val);
                    } else {
                        val += bias[col];
                        Df[(size_t)row * FF + col] = fmaxf(val, 0.f);
                    }
                }
            }
        }
    }
}

// ---------------------------------------------------------------------------
extern "C" void kernel_launch(void* const* d_in, const int* in_sizes, int n_in,
                              void* d_out, int out_size)
{
    const float* q    = (const float*)d_in[0];
    const float* k    = (const float*)d_in[1];
    const float* v    = (const float*)d_in[2];
    const float* wq_w = (const float*)d_in[3];
    const float* wq_b = (const float*)d_in[4];
    const float* wk_w = (const float*)d_in[5];
    const float* wk_b = (const float*)d_in[6];
    const float* wv_w = (const float*)d_in[7];
    const float* wv_b = (const float*)d_in[8];
    const float* fc_w = (const float*)d_in[9];
    const float* fc_b = (const float*)d_in[10];

    float* out  = (float*)d_out;
    float* attn = out + (size_t)BB * SS * FF;

    uint16_t *wq_h, *wq_l, *wk_h, *wk_l, *wv_h, *wv_l, *fcw_h, *fcw_l;
    uint16_t *qh_h, *qh_l, *kh_h, *kh_l, *vt_h, *vt_l, *ctx_h, *ctx_l;
    float *part, *inv;
    cudaGetSymbolAddress((void**)&wq_h, g_wq_h); cudaGetSymbolAddress((void**)&wq_l, g_wq_l);
    cudaGetSymbolAddress((void**)&wk_h, g_wk_h); cudaGetSymbolAddress((void**)&wk_l, g_wk_l);
    cudaGetSymbolAddress((void**)&wv_h, g_wv_h); cudaGetSymbolAddress((void**)&wv_l, g_wv_l);
    cudaGetSymbolAddress((void**)&fcw_h, g_fcw_h); cudaGetSymbolAddress((void**)&fcw_l, g_fcw_l);
    cudaGetSymbolAddress((void**)&qh_h, g_qh_h); cudaGetSymbolAddress((void**)&qh_l, g_qh_l);
    cudaGetSymbolAddress((void**)&kh_h, g_kh_h); cudaGetSymbolAddress((void**)&kh_l, g_kh_l);
    cudaGetSymbolAddress((void**)&vt_h, g_vt_h); cudaGetSymbolAddress((void**)&vt_l, g_vt_l);
    cudaGetSymbolAddress((void**)&ctx_h, g_ctx_h); cudaGetSymbolAddress((void**)&ctx_l, g_ctx_l);
    cudaGetSymbolAddress((void**)&part, g_part);  cudaGetSymbolAddress((void**)&inv, g_inv);

    const int SM_PROJ = (128 * 40 * 2 + 128 * 40 * 2) * 2;  // 40960
    const int SM_SCOR = (128 * 72 * 2 + 128 * 72 * 2) * 2;  // 73728
    const int SM_CTX  = (128 * 40 * 2 + 64 * 40 * 2) * 2;   // 30720

    cudaFuncSetAttribute(mma_gemm<0>, cudaFuncAttributeMaxDynamicSharedMemorySize, SM_PROJ);
    cudaFuncSetAttribute(mma_gemm<1>, cudaFuncAttributeMaxDynamicSharedMemorySize, SM_PROJ);
    cudaFuncSetAttribute(mma_gemm<2>, cudaFuncAttributeMaxDynamicSharedMemorySize, SM_SCOR);
    cudaFuncSetAttribute(mma_gemm<3>, cudaFuncAttributeMaxDynamicSharedMemorySize, SM_CTX);
    cudaFuncSetAttribute(mma_gemm<4>, cudaFuncAttributeMaxDynamicSharedMemorySize, SM_PROJ);

    presplit_kernel<<<256, 256>>>((const float4*)wq_w, wq_h, wq_l);
    presplit_kernel<<<256, 256>>>((const float4*)wk_w, wk_h, wk_l);
    presplit_kernel<<<256, 256>>>((const float4*)wv_w, wv_h, wv_l);
    presplit_kernel<<<256, 256>>>((const float4*)fc_w, fcw_h, fcw_l);

    dim3 gProj(FF / 128, (BB * SS) / 128);     // (8, 64)
    mma_gemm<0><<<gProj, 256, SM_PROJ>>>(nullptr, nullptr, q, wq_h, wq_l, wq_b,
                                         nullptr, qh_h, qh_l, nullptr, nullptr);
    mma_gemm<0><<<gProj, 256, SM_PROJ>>>(nullptr, nullptr, k, wk_h, wk_l, wk_b,
                                         nullptr, kh_h, kh_l, nullptr, nullptr);
    mma_gemm<1><<<gProj, 256, SM_PROJ>>>(nullptr, nullptr, v, wv_h, wv_l, wv_b,
                                         nullptr, vt_h, vt_l, nullptr, nullptr);

    dim3 gS(SS / 128, SS / 128, BB * HH);      // (16, 16, 64)
    mma_gemm<2><<<gS, 256, SM_SCOR>>>(qh_h, qh_l, nullptr, kh_h, kh_l, nullptr,
                                      attn, nullptr, nullptr, part, nullptr);

    rowinv_kernel<<<BB * HH * SS / 256, 256>>>(part, inv);

    dim3 gC(1, SS / 128, BB * HH);             // (1, 16, 64)
    mma_gemm<3><<<gC, 256, SM_CTX>>>(nullptr, nullptr, attn, vt_h, vt_l, nullptr,
                                     attn, ctx_h, ctx_l, nullptr, inv);

    mma_gemm<4><<<gProj, 256, SM_PROJ>>>(ctx_h, ctx_l, nullptr, fcw_h, fcw_l, fc_b,
                                         out, nullptr, nullptr, nullptr, nullptr);
}